// round 1
// baseline (speedup 1.0000x reference)
#include <cuda_runtime.h>

// ---------------------------------------------------------------------------
// SSD post-process: softmax -> threshold -> top-512 -> decode -> IoU -> NMS
// ---------------------------------------------------------------------------

#define N_MAX    (1u << 21)
#define NBINS    16384
#define BASEBITS 0x3F666666u        // bits(0.9f) - 1
#define KTOP     512
#define SELCAP   1024
#define PREF_T   2.19f              // conservative prefilter: ln(9)=2.1972

__device__ unsigned long long g_cands[N_MAX];     // 16MB scratch (static, allowed)
__device__ int                g_hist[NBINS];
__device__ int                g_cand_count;
__device__ int                g_sel_count;
__device__ int                g_cutoff;
__device__ unsigned long long g_sel[SELCAP];
__device__ float4             g_box[KTOP];        // pixel coords x1,y1,x2,y2
__device__ float              g_area[KTOP];
__device__ float              g_score[KTOP];
__device__ unsigned int       g_mask32[KTOP * 16]; // 512x512 suppression bits

// ---------------------------------------------------------------------------
// Kernel 0: reset counters + histogram (graph is replayed; must re-zero)
// ---------------------------------------------------------------------------
__global__ void k_reset() {
    int i = blockIdx.x * blockDim.x + threadIdx.x;
    if (i < NBINS)            g_hist[i] = 0;
    else if (i == NBINS)      g_cand_count = 0;
    else if (i == NBINS + 1)  g_sel_count = 0;
}

// ---------------------------------------------------------------------------
// Kernel 1: scan conf, threshold, emit candidates (block-aggregated) + histogram
// ---------------------------------------------------------------------------
__global__ void __launch_bounds__(256) k_scan(const float2* __restrict__ conf, int n) {
    __shared__ unsigned long long lbuf[2048];
    __shared__ int lcount, lbase;
    int tid  = threadIdx.x;
    int lane = tid & 31;
    if (tid == 0) lcount = 0;
    __syncthreads();

    int base = blockIdx.x * 2048;
#pragma unroll
    for (int k = 0; k < 8; ++k) {
        int i = base + k * 256 + tid;
        bool pass = false;
        float s = 0.0f;
        if (i < n) {
            float2 c = conf[i];                   // c.x = conf0, c.y = conf1
            if (c.y - c.x > PREF_T) {
                // mirror jax softmax: 1 / (1 + exp(c0 - c1)) in fp32
                s = 1.0f / (1.0f + expf(c.x - c.y));
                pass = s > 0.9f;
            }
        }
        unsigned m = __ballot_sync(0xffffffffu, pass);
        if (m) {
            int pos0 = 0;
            int lead = __ffs(m) - 1;
            if (lane == lead) pos0 = atomicAdd(&lcount, __popc(m));
            pos0 = __shfl_sync(0xffffffffu, pos0, lead);
            if (pass) {
                int pos = pos0 + __popc(m & ((1u << lane) - 1u));
                unsigned sb = __float_as_uint(s);
                // key: score desc, then lowest index first (matches lax.top_k)
                lbuf[pos] = ((unsigned long long)sb << 32) |
                            (unsigned long long)(0xffffffffu - (unsigned)i);
                unsigned bin = (sb - BASEBITS) >> 7;
                if (bin >= NBINS) bin = NBINS - 1;
                atomicAdd(&g_hist[bin], 1);       // scattered over 16K bins: cheap
            }
        }
    }
    __syncthreads();
    if (tid == 0) lbase = atomicAdd(&g_cand_count, lcount);  // 1 atomic / block
    __syncthreads();
    for (int j = tid; j < lcount; j += 256) g_cands[lbase + j] = lbuf[j];
}

// ---------------------------------------------------------------------------
// Kernel 2: suffix-scan histogram from the top -> bin containing rank 512
// ---------------------------------------------------------------------------
__global__ void k_cutoff() {
    __shared__ int csum[256];
    int tid = threadIdx.x;
    int acc = 0;
#pragma unroll 8
    for (int b = 0; b < 64; ++b) acc += g_hist[tid * 64 + b];
    csum[tid] = acc;
    __syncthreads();
    if (tid == 0) {
        int a = 0, cutoff = 0;
        for (int c = 255; c >= 0; --c) {
            if (a + csum[c] >= KTOP) {
                for (int b = c * 64 + 63; b >= c * 64; --b) {
                    a += g_hist[b];
                    if (a >= KTOP) { cutoff = b; break; }
                }
                break;
            }
            a += csum[c];
        }
        g_cutoff = cutoff;
    }
}

// ---------------------------------------------------------------------------
// Kernel 3: compact candidates with bin >= cutoff  (~515 survive)
// ---------------------------------------------------------------------------
__global__ void k_compact() {
    int n = g_cand_count;
    if (n > (int)N_MAX) n = N_MAX;
    int cut = g_cutoff;
    int stride = gridDim.x * blockDim.x;
    for (int i = blockIdx.x * blockDim.x + threadIdx.x; i < n; i += stride) {
        unsigned long long key = g_cands[i];
        unsigned sb  = (unsigned)(key >> 32);
        unsigned bin = (sb - BASEBITS) >> 7;
        if (bin >= NBINS) bin = NBINS - 1;
        if ((int)bin >= cut) {
            int p = atomicAdd(&g_sel_count, 1);
            if (p < SELCAP) g_sel[p] = key;
        }
    }
}

// ---------------------------------------------------------------------------
// Kernel 4a: bitonic sort (desc) of <=1024 keys, take top 512, decode boxes
// ---------------------------------------------------------------------------
__global__ void __launch_bounds__(1024) k_sort_decode(const float4* __restrict__ loc,
                                                      const float4* __restrict__ priors) {
    __shared__ unsigned long long sbuf[SELCAP];
    int tid = threadIdx.x;
    int n = g_sel_count;
    if (n > SELCAP) n = SELCAP;
    sbuf[tid] = (tid < n) ? g_sel[tid] : 0ull;
    __syncthreads();

    for (int k = 2; k <= SELCAP; k <<= 1) {
        for (int j = k >> 1; j; j >>= 1) {
            int ixj = tid ^ j;
            if (ixj > tid) {
                unsigned long long a = sbuf[tid], b = sbuf[ixj];
                if (((tid & k) == 0) ? (a < b) : (a > b)) {
                    sbuf[tid] = b; sbuf[ixj] = a;
                }
            }
            __syncthreads();
        }
    }

    if (tid < KTOP) {
        unsigned long long key = sbuf[tid];
        float X1 = 0.f, Y1 = 0.f, X2 = 0.f, Y2 = 0.f, score = -1.0f;
        if (key != 0ull) {
            score = __uint_as_float((unsigned)(key >> 32));
            unsigned idx = 0xffffffffu - (unsigned)(key & 0xffffffffu);
            float4 l = loc[idx];
            float4 p = priors[idx];
            // mirror reference op order, no FMA contraction
            float cx = __fadd_rn(p.x, __fmul_rn(__fmul_rn(l.x, 0.1f), p.z));
            float cy = __fadd_rn(p.y, __fmul_rn(__fmul_rn(l.y, 0.1f), p.w));
            float w  = __fmul_rn(p.z, expf(__fmul_rn(l.z, 0.2f)));
            float h  = __fmul_rn(p.w, expf(__fmul_rn(l.w, 0.2f)));
            float x1 = __fsub_rn(cx, __fmul_rn(w, 0.5f));
            float y1 = __fsub_rn(cy, __fmul_rn(h, 0.5f));
            float x2 = __fadd_rn(x1, w);
            float y2 = __fadd_rn(y1, h);
            X1 = __fmul_rn(x1, 2048.0f);  // exact (power of two)
            Y1 = __fmul_rn(y1, 2048.0f);
            X2 = __fmul_rn(x2, 2048.0f);
            Y2 = __fmul_rn(y2, 2048.0f);
        }
        g_box[tid]   = make_float4(X1, Y1, X2, Y2);
        g_area[tid]  = __fmul_rn(__fadd_rn(__fsub_rn(X2, X1), 1.0f),
                                 __fadd_rn(__fsub_rn(Y2, Y1), 1.0f));
        g_score[tid] = score;
    }
}

// ---------------------------------------------------------------------------
// Kernel 4b: 512x512 suppression bitmask, spread over the chip
// 32768 threads; thread T -> row i = T>>6, 8 columns starting at (T&63)*8
// ---------------------------------------------------------------------------
__global__ void __launch_bounds__(256) k_iou() {
    int T  = blockIdx.x * blockDim.x + threadIdx.x;   // 0..32767
    int i  = T >> 6;
    int j0 = (T & 63) << 3;
    unsigned bits = 0u;
    float si = g_score[i];
    if (si > 0.0f) {                                   // invalid rows never suppress
        float4 bi = g_box[i];
        float  ai = g_area[i];
#pragma unroll
        for (int b = 0; b < 8; ++b) {
            int j = j0 + b;
            float4 bj = g_box[j];
            float xx1 = fmaxf(bi.x, bj.x);
            float yy1 = fmaxf(bi.y, bj.y);
            float xx2 = fminf(bi.z, bj.z);
            float yy2 = fminf(bi.w, bj.w);
            float w = fmaxf(__fadd_rn(__fsub_rn(xx2, xx1), 1.0f), 0.0f);
            float h = fmaxf(__fadd_rn(__fsub_rn(yy2, yy1), 1.0f), 0.0f);
            float inter = __fmul_rn(w, h);
            float uni = __fsub_rn(__fadd_rn(ai, g_area[j]), inter);
            // iou > 0.4  <=>  inter > 0.4*union   (union > 0 always; kills division)
            if (j > i && inter > __fmul_rn(0.4f, uni)) bits |= 1u << b;
        }
    }
    ((unsigned char*)g_mask32)[T] = (unsigned char)bits;  // LE byte order = bit order
}

// ---------------------------------------------------------------------------
// Kernel 4c: serial greedy NMS (warp-cooperative bitset) + write output
// ---------------------------------------------------------------------------
__global__ void __launch_bounds__(512) k_nms_out(float* __restrict__ out) {
    __shared__ unsigned um[KTOP * 16];   // 32KB suppression matrix
    __shared__ unsigned keepw[16];
    int tid = threadIdx.x;
    for (int w = tid; w < KTOP * 16; w += 512) um[w] = g_mask32[w];
    __syncthreads();

    if (tid < 32) {
        unsigned rem = 0u;               // lanes 0..15 own removal words
        for (int i = 0; i < KTOP; ++i) {
            unsigned rw = __shfl_sync(0xffffffffu, rem, i >> 5);
            if (!((rw >> (i & 31)) & 1u)) {
                unsigned m = (tid < 16) ? um[(i << 4) + tid] : 0u;
                rem |= m;
            }
        }
        if (tid < 16) keepw[tid] = rem;
    }
    __syncthreads();

    if (tid < KTOP) {
        float sc = g_score[tid];
        bool kept = (sc > 0.0f) && !((keepw[tid >> 5] >> (tid & 31)) & 1u);
        float4 b = g_box[tid];
        const float inv = 1.0f / 2048.0f;           // exact
        out[tid * 5 + 0] = kept ? __fmul_rn(b.x, inv) : 0.0f;
        out[tid * 5 + 1] = kept ? __fmul_rn(b.y, inv) : 0.0f;
        out[tid * 5 + 2] = kept ? __fmul_rn(b.z, inv) : 0.0f;
        out[tid * 5 + 3] = kept ? __fmul_rn(b.w, inv) : 0.0f;
        out[tid * 5 + 4] = kept ? sc : 0.0f;
    }
}

// ---------------------------------------------------------------------------
extern "C" void kernel_launch(void* const* d_in, const int* in_sizes, int n_in,
                              void* d_out, int out_size) {
    const float4* loc    = (const float4*)d_in[0];   // [N,4]
    const float2* conf   = (const float2*)d_in[1];   // [N,2]
    const float4* priors = (const float4*)d_in[2];   // [N,4]
    float* out = (float*)d_out;                      // [512,5]
    int n = in_sizes[0] / 4;

    k_reset<<<(NBINS + 2 + 255) / 256, 256>>>();
    k_scan<<<(n + 2047) / 2048, 256>>>(conf, n);
    k_cutoff<<<1, 256>>>();
    k_compact<<<256, 256>>>();
    k_sort_decode<<<1, 1024>>>(loc, priors);
    k_iou<<<128, 256>>>();
    k_nms_out<<<1, 512>>>(out);
}

// round 2
// speedup vs baseline: 1.7407x; 1.7407x over previous
#include <cuda_runtime.h>

// ---------------------------------------------------------------------------
// SSD post-process, fused into 3 kernels:
//  K1: conf scan -> prefilter -> exact softmax -> candidate emit + score histogram
//  K2: per-block cutoff from histogram -> compact -> [last block] bitonic sort
//      (score desc, idx asc) -> decode top-512 boxes
//  K3: 512x512 suppression bitmask (multi-block) -> [last block] greedy NMS
//      -> output + tail reset of all counters/histogram for the next replay
// ---------------------------------------------------------------------------

#define N_MAX    (1u << 21)
#define NB       4096               // histogram bins over score bits
#define BSHIFT   9                  // 512-ulp bins
#define BASEBITS 0x3F666666u        // bits(0.9f) - 1
#define KTOP     512
#define SELCAP   1024
#define PREF_T   2.19f              // conservative prefilter: ln(9)=2.1972

__device__ unsigned long long      g_cands[N_MAX];
__device__ __align__(16) int       g_hist[NB];
__device__ int                     g_cand_count;
__device__ int                     g_sel_count;
__device__ unsigned                g_tick2;
__device__ unsigned                g_tick3;
__device__ unsigned long long      g_sel[SELCAP];
__device__ float4                  g_box[KTOP];
__device__ float                   g_area[KTOP];
__device__ float                   g_score[KTOP];
__device__ unsigned                g_mask32[KTOP * 16];

// ---------------------------------------------------------------------------
// K1: scan conf (float4 = 2 priors/load), emit candidates + histogram.
// One block covers 2048 priors. Block-aggregated global writes.
// ---------------------------------------------------------------------------
__global__ void __launch_bounds__(256) k_scan(const float4* __restrict__ conf4, int n4) {
    __shared__ unsigned long long lbuf[2048];
    __shared__ int lcount, lbase;
    int tid  = threadIdx.x;
    int lane = tid & 31;
    unsigned lt = (1u << lane) - 1u;
    if (tid == 0) lcount = 0;
    __syncthreads();

    int base = blockIdx.x * 1024;          // in float4 units
#pragma unroll
    for (int k = 0; k < 4; ++k) {
        int i4 = base + k * 256 + tid;
        bool p0 = false, p1 = false;
        float s0 = 0.f, s1 = 0.f;
        if (i4 < n4) {
            float4 c = conf4[i4];          // (c0,c1) for prior 2*i4, (c0,c1) for 2*i4+1
            if (c.y - c.x > PREF_T) {
                s0 = 1.0f / (1.0f + expf(c.x - c.y));
                p0 = s0 > 0.9f;
            }
            if (c.w - c.z > PREF_T) {
                s1 = 1.0f / (1.0f + expf(c.z - c.w));
                p1 = s1 > 0.9f;
            }
        }
        unsigned m0 = __ballot_sync(0xffffffffu, p0);
        unsigned m1 = __ballot_sync(0xffffffffu, p1);
        int cnt = __popc(m0) + __popc(m1);
        if (cnt) {
            int b0 = 0;
            if (lane == 0) b0 = atomicAdd(&lcount, cnt);
            b0 = __shfl_sync(0xffffffffu, b0, 0);
            if (p0) {
                unsigned sb = __float_as_uint(s0);
                unsigned idx = 2u * (unsigned)i4;
                lbuf[b0 + __popc(m0 & lt)] =
                    ((unsigned long long)sb << 32) | (unsigned long long)(0xffffffffu - idx);
                atomicAdd(&g_hist[(sb - BASEBITS) >> BSHIFT], 1);
            }
            if (p1) {
                unsigned sb = __float_as_uint(s1);
                unsigned idx = 2u * (unsigned)i4 + 1u;
                lbuf[b0 + __popc(m0) + __popc(m1 & lt)] =
                    ((unsigned long long)sb << 32) | (unsigned long long)(0xffffffffu - idx);
                atomicAdd(&g_hist[(sb - BASEBITS) >> BSHIFT], 1);
            }
        }
    }
    __syncthreads();
    if (tid == 0) lbase = atomicAdd(&g_cand_count, lcount);
    __syncthreads();
    for (int j = tid; j < lcount; j += 256) g_cands[lbase + j] = lbuf[j];
}

// ---------------------------------------------------------------------------
// K2: every block computes the cutoff bin from the histogram (redundant,
// L2-resident), compacts its slice of candidates; the LAST block to retire
// sorts the <=1024 survivors and decodes the top 512.
// ---------------------------------------------------------------------------
__global__ void __launch_bounds__(1024) k_select(const float4* __restrict__ loc,
                                                 const float4* __restrict__ priors) {
    __shared__ int s_h[NB];                     // 16KB
    __shared__ int s_suf[1024];                 // 4KB
    __shared__ int s_cut;
    __shared__ int s_last;
    __shared__ unsigned long long sbuf[SELCAP]; // 8KB
    int tid = threadIdx.x;

    // cutoff: suffix-scan over 4-bin groups
    int4 hv = ((const int4*)g_hist)[tid];
    s_h[4 * tid + 0] = hv.x; s_h[4 * tid + 1] = hv.y;
    s_h[4 * tid + 2] = hv.z; s_h[4 * tid + 3] = hv.w;
    s_suf[tid] = hv.x + hv.y + hv.z + hv.w;
    if (tid == 0) s_cut = 0;
    __syncthreads();
    for (int st = 1; st < 1024; st <<= 1) {
        int v = s_suf[tid];
        int w = (tid + st < 1024) ? s_suf[tid + st] : 0;
        __syncthreads();
        s_suf[tid] = v + w;
        __syncthreads();
    }
    {
        int St  = s_suf[tid];
        int Stn = (tid < 1023) ? s_suf[tid + 1] : 0;
        if (St >= KTOP && Stn < KTOP) {   // cutoff lies in this 4-bin group
            int run = Stn, b;
            for (b = 4 * tid + 3; b >= 4 * tid; --b) {
                run += s_h[b];
                if (run >= KTOP) break;
            }
            s_cut = b;                    // largest bin with suffix >= KTOP
        }
    }
    __syncthreads();
    int cut = s_cut;

    // compact candidates with bin >= cut
    int n = g_cand_count;
    if (n > (int)N_MAX) n = N_MAX;
    int total = gridDim.x * 1024;
    for (int i = blockIdx.x * 1024 + tid; i < n; i += total) {
        unsigned long long key = g_cands[i];
        int bin = (int)(((unsigned)(key >> 32) - BASEBITS) >> BSHIFT);
        if (bin >= cut) {
            int p = atomicAdd(&g_sel_count, 1);
            if (p < SELCAP) g_sel[p] = key;
        }
    }
    __threadfence();
    __syncthreads();
    if (tid == 0) s_last = (atomicAdd(&g_tick2, 1u) == gridDim.x - 1);
    __syncthreads();
    if (!s_last) return;

    // ---- last block: bitonic sort (desc) + decode ----
    int ns = atomicAdd(&g_sel_count, 0);
    if (ns > SELCAP) ns = SELCAP;
    sbuf[tid] = (tid < ns) ? g_sel[tid] : 0ull;
    __syncthreads();
    for (int k = 2; k <= SELCAP; k <<= 1) {
        for (int j = k >> 1; j; j >>= 1) {
            int ixj = tid ^ j;
            if (ixj > tid) {
                unsigned long long a = sbuf[tid], b = sbuf[ixj];
                if (((tid & k) == 0) ? (a < b) : (a > b)) {
                    sbuf[tid] = b; sbuf[ixj] = a;
                }
            }
            __syncthreads();
        }
    }
    if (tid < KTOP) {
        unsigned long long key = sbuf[tid];
        float X1 = 0.f, Y1 = 0.f, X2 = 0.f, Y2 = 0.f, score = -1.0f;
        if (key != 0ull) {
            score = __uint_as_float((unsigned)(key >> 32));
            unsigned idx = 0xffffffffu - (unsigned)(key & 0xffffffffu);
            float4 l = loc[idx];
            float4 p = priors[idx];
            float cx = __fadd_rn(p.x, __fmul_rn(__fmul_rn(l.x, 0.1f), p.z));
            float cy = __fadd_rn(p.y, __fmul_rn(__fmul_rn(l.y, 0.1f), p.w));
            float w  = __fmul_rn(p.z, expf(__fmul_rn(l.z, 0.2f)));
            float h  = __fmul_rn(p.w, expf(__fmul_rn(l.w, 0.2f)));
            float x1 = __fsub_rn(cx, __fmul_rn(w, 0.5f));
            float y1 = __fsub_rn(cy, __fmul_rn(h, 0.5f));
            float x2 = __fadd_rn(x1, w);
            float y2 = __fadd_rn(y1, h);
            X1 = __fmul_rn(x1, 2048.0f);
            Y1 = __fmul_rn(y1, 2048.0f);
            X2 = __fmul_rn(x2, 2048.0f);
            Y2 = __fmul_rn(y2, 2048.0f);
        }
        g_box[tid]   = make_float4(X1, Y1, X2, Y2);
        g_area[tid]  = __fmul_rn(__fadd_rn(__fsub_rn(X2, X1), 1.0f),
                                 __fadd_rn(__fsub_rn(Y2, Y1), 1.0f));
        g_score[tid] = score;
    }
}

// ---------------------------------------------------------------------------
// K3: suppression bitmask spread over the chip; the last block to retire does
// the serial greedy NMS (chunked, register-resident diagonal), writes the
// output, and resets all global state for the next graph replay.
// ---------------------------------------------------------------------------
__global__ void __launch_bounds__(256) k_iou_nms(float* __restrict__ out) {
    int tid = threadIdx.x;
    int T   = blockIdx.x * 256 + tid;     // 0..32767
    {
        int i  = T >> 6;
        int j0 = (T & 63) << 3;
        unsigned bits = 0u;
        float si = g_score[i];
        if (si > 0.0f) {
            float4 bi = g_box[i];
            float  ai = g_area[i];
#pragma unroll
            for (int b = 0; b < 8; ++b) {
                int j = j0 + b;
                float4 bj = g_box[j];
                float xx1 = fmaxf(bi.x, bj.x);
                float yy1 = fmaxf(bi.y, bj.y);
                float xx2 = fminf(bi.z, bj.z);
                float yy2 = fminf(bi.w, bj.w);
                float w = fmaxf(__fadd_rn(__fsub_rn(xx2, xx1), 1.0f), 0.0f);
                float h = fmaxf(__fadd_rn(__fsub_rn(yy2, yy1), 1.0f), 0.0f);
                float inter = __fmul_rn(w, h);
                float uni = __fsub_rn(__fadd_rn(ai, g_area[j]), inter);
                if (j > i && inter > __fmul_rn(0.4f, uni)) bits |= 1u << b;
            }
        }
        ((unsigned char*)g_mask32)[T] = (unsigned char)bits;
    }

    __threadfence();
    __shared__ int s_last;
    __syncthreads();
    if (tid == 0) s_last = (atomicAdd(&g_tick3, 1u) == gridDim.x - 1);
    __syncthreads();
    if (!s_last) return;

    // ---- last block: NMS + output + tail reset ----
    __shared__ unsigned um[KTOP * 16];    // 32KB
    __shared__ unsigned s_keepw[16];
    for (int w = tid; w < KTOP * 16; w += 256) um[w] = g_mask32[w];
    __syncthreads();

    if (tid < 32) {
        unsigned rem = 0u;                // lanes 0..15 own column words
        for (int c = 0; c < 16; ++c) {
            unsigned val = __shfl_sync(0xffffffffu, rem, c);
            unsigned dm[32];
#pragma unroll
            for (int r = 0; r < 32; ++r) dm[r] = um[(c * 32 + r) * 16 + c]; // bcast LDS
#pragma unroll
            for (int r = 0; r < 32; ++r) {
                if (!((val >> r) & 1u)) val |= dm[r];   // j>i guaranteed by mask
            }
            unsigned keep = ~val;         // kept rows within chunk c (all lanes agree)
            if (tid < 16) {
#pragma unroll
                for (int r = 0; r < 32; ++r) {
                    if ((keep >> r) & 1u) rem |= um[(c * 32 + r) * 16 + tid];
                }
            }
        }
        if (tid < 16) s_keepw[tid] = rem;
    }
    __syncthreads();

    const float inv = 1.0f / 2048.0f;     // exact
    for (int r = tid; r < KTOP; r += 256) {
        float sc = g_score[r];
        bool kept = (sc > 0.0f) && !((s_keepw[r >> 5] >> (r & 31)) & 1u);
        float4 b = g_box[r];
        out[r * 5 + 0] = kept ? __fmul_rn(b.x, inv) : 0.0f;
        out[r * 5 + 1] = kept ? __fmul_rn(b.y, inv) : 0.0f;
        out[r * 5 + 2] = kept ? __fmul_rn(b.z, inv) : 0.0f;
        out[r * 5 + 3] = kept ? __fmul_rn(b.w, inv) : 0.0f;
        out[r * 5 + 4] = kept ? sc : 0.0f;
    }

    // tail reset for next call (globals are zero-initialized for the first)
    for (int i = tid; i < NB; i += 256) g_hist[i] = 0;
    if (tid == 0) {
        g_cand_count = 0;
        g_sel_count  = 0;
        g_tick2      = 0u;
        g_tick3      = 0u;
    }
}

// ---------------------------------------------------------------------------
extern "C" void kernel_launch(void* const* d_in, const int* in_sizes, int n_in,
                              void* d_out, int out_size) {
    const float4* loc    = (const float4*)d_in[0];   // [N,4]
    const float4* conf4  = (const float4*)d_in[1];   // [N,2] as float4 pairs
    const float4* priors = (const float4*)d_in[2];   // [N,4]
    float* out = (float*)d_out;                      // [512,5]
    int n  = in_sizes[0] / 4;
    int n4 = n >> 1;

    k_scan  <<<(n4 + 1023) / 1024, 256>>>(conf4, n4);
    k_select<<<64, 1024>>>(loc, priors);
    k_iou_nms<<<128, 256>>>(out);
}